// round 15
// baseline (speedup 1.0000x reference)
#include <cuda_runtime.h>
#include <cuda_bf16.h>
#include <math.h>
#include <stdint.h>

#define E_DIM 512
#define BLROWS 16384
#define NRR 100
#define NPAD 112                        // 14 n-tiles of 8
#define NORM_TERM 10.82490511970208f    // ln(50257)
#define LOG_NR 4.605170185988092f       // ln(100)
#define MROWS 64                        // rows per CTA
#define ASTR 144                        // bf16 A-tile row stride (72 bf16)
#define ASUB 9216                       // one 64-k sub-tile (64 rows x 144B)
#define APAIR 18432                     // 128-k A stage (2 sub-tiles)
#define GSTAGE 32768                    // 128-k f32 gather stage (64 rows x 512B)
#define NBLK 256

// B fragment table: [kstep(32)][ngrp(2)][pair(4)][lane(32)] x uint4
// uint4 = {t0.b0, t0.b1, t1.b0, t1.b1}, tiles t0=grp*7+pair*2, t1=t0+1.
// pair==3 high half (phantom tile 7/13) is zero.
__device__ __align__(16) uint4 g_bf4[32 * 2 * 4 * 32];   // 131072 B
__device__ float g_part[NBLK];
__device__ int   g_ctr = 0;             // self-resetting (graph-replay safe)

__device__ __forceinline__ uint32_t smem_u32(const void* p) {
    uint32_t a;
    asm("{ .reg .u64 t; cvta.to.shared.u64 t, %1; cvt.u32.u64 %0, t; }" : "=r"(a) : "l"(p));
    return a;
}
__device__ __forceinline__ void cp_async16(uint32_t dst, const void* src) {
    asm volatile("cp.async.cg.shared.global [%0], [%1], 16;" :: "r"(dst), "l"(src) : "memory");
}
#define CP_COMMIT() asm volatile("cp.async.commit_group;" ::: "memory")
#define CP_WAIT1()  asm volatile("cp.async.wait_group 1;" ::: "memory")
__device__ __forceinline__ void ldmatrix_x4(uint32_t& r0, uint32_t& r1,
                                            uint32_t& r2, uint32_t& r3, uint32_t addr) {
    asm volatile("ldmatrix.sync.aligned.m8n8.x4.shared.b16 {%0,%1,%2,%3}, [%4];"
                 : "=r"(r0), "=r"(r1), "=r"(r2), "=r"(r3) : "r"(addr));
}
__device__ __forceinline__ void mma16816(float* d, const uint32_t* a,
                                         uint32_t b0, uint32_t b1) {
    asm volatile("mma.sync.aligned.m16n8k16.row.col.f32.bf16.bf16.f32 "
                 "{%0,%1,%2,%3}, {%4,%5,%6,%7}, {%8,%9}, {%0,%1,%2,%3};"
                 : "+f"(d[0]), "+f"(d[1]), "+f"(d[2]), "+f"(d[3])
                 : "r"(a[0]), "r"(a[1]), "r"(a[2]), "r"(a[3]), "r"(b0), "r"(b1));
}
__device__ __forceinline__ float softplus_exact(float x) {
    return fmaxf(x, 0.0f) + log1pf(expf(-fabsf(x)));
}
__device__ __forceinline__ uint2 cvt_bf16x4(float4 v) {
    __nv_bfloat162 p0 = __float22bfloat162_rn(make_float2(v.x, v.y));
    __nv_bfloat162 p1 = __float22bfloat162_rn(make_float2(v.z, v.w));
    uint2 r;
    r.x = *reinterpret_cast<uint32_t*>(&p0);
    r.y = *reinterpret_cast<uint32_t*>(&p1);
    return r;
}

// ---------------------------------------------------------------------------
// Prep: build the B fragment table (one u32 per thread, 32768 total).
// ---------------------------------------------------------------------------
__global__ void prep_kernel(const float* __restrict__ emb,
                            const int* __restrict__ nidx) {
    int u = blockIdx.x * blockDim.x + threadIdx.x;
    if (u >= 32768) return;
    int comp = u & 3;                   // {t0.b0, t0.b1, t1.b0, t1.b1}
    int e = u >> 2;
    int lane = e & 31;
    int pair = (e >> 5) & 3;
    int grp  = (e >> 7) & 1;
    int s    = e >> 8;                  // kstep 0..31
    int tile = grp * 7 + pair * 2 + (comp >> 1);
    uint32_t val = 0;
    if (!(pair == 3 && (comp >> 1) == 1)) {
        int n = tile * 8 + (lane >> 2);
        if (n < NRR) {
            int k = s * 16 + (lane & 3) * 2 + (comp & 1) * 8;
            const float* src = emb + (size_t)nidx[n] * E_DIM + k;
            __nv_bfloat162 pk = __float22bfloat162_rn(make_float2(src[0], src[1]));
            val = *reinterpret_cast<uint32_t*>(&pk);
        }
    }
    reinterpret_cast<uint32_t*>(g_bf4)[e * 4 + comp] = val;
}

// ---------------------------------------------------------------------------
// Main: 64-row CTAs, 256 thr, 2/SM. 4 iterations of K=128 (2 sub-chunks),
// ONE __syncthreads per iteration (4 total). A: 2x18.4KB stages; gather:
// 2x32.8KB cp.async stages (wg1 schedule, stage reuse sync-protected);
// B straight from the L1/L2-hot fragment table; input register prefetch.
// ---------------------------------------------------------------------------
__global__ void __launch_bounds__(256, 2)
mega_kernel(const float* __restrict__ inp,
            const float* __restrict__ emb,
            const float* __restrict__ bias,
            const float* __restrict__ lpn,
            const int*   __restrict__ tgt,
            const int*   __restrict__ nidx,
            float* __restrict__ out) {
    extern __shared__ char dsm[];
    __shared__ float cs[NPAD];
    __shared__ int   s_t[MROWS];
    __shared__ float s_xc[MROWS];
    __shared__ float s_tdot[MROWS];
    __shared__ float s_red[2][MROWS];
    __shared__ float s_fin[MROWS];
    __shared__ int   s_flag;

    const int tid = threadIdx.x;
    const int lane = tid & 31;
    const int row0 = blockIdx.x * MROWS;

    const uint32_t db = smem_u32(dsm);
    const uint32_t abase = (db + 1023u) & ~1023u;
    const uint32_t gbase = abase + 2 * APAIR;
    char* ap = dsm + (abase - db);
    char* gp = dsm + (gbase - db);

    if (tid < NPAD) {
        int nv = (tid < NRR) ? nidx[tid] : -1;
        cs[tid] = (tid < NRR) ? (bias[nv] - NORM_TERM - lpn[nv] - LOG_NR) : -1e30f;
    }
    if (tid >= 128 && tid < 128 + MROWS) {
        int r = tid - 128;
        int t = tgt[row0 + r];
        s_t[r] = t;
        s_xc[r] = bias[t] - NORM_TERM - lpn[t] - LOG_NR;
    }
    __syncthreads();

    // ---------------- per-thread layout ----------------
    const int l4 = tid & 15;            // 16B k-slot
    const int rg = tid >> 4;            // 0..15; rows rg+16j
    const float* ipt = inp + (size_t)(row0 + rg) * E_DIM + l4 * 4;
    const uint32_t asts = (uint32_t)rg * ASTR + l4 * 8;

    // gather: row stride 512B per stage; 8 cp.async per pair (4 rows x 2 subs)
    const char* embB = (const char*)emb;
    uint32_t gsrc[4], gdst[4];
#pragma unroll
    for (int i = 0; i < 4; i++) {
        int row = rg + 16 * i;
        gsrc[i] = (uint32_t)s_t[row] * 2048u + (uint32_t)l4 * 16u;
        gdst[i] = (uint32_t)row * 512u + (uint32_t)l4 * 16u;
    }

    // MMA fragment addressing
    const int m0 = (tid >> 5 & 3) * 16;
    const int ngrp = tid >> 7;
    const uint32_t a_woff = (uint32_t)(m0 + (lane & 15)) * ASTR + ((lane >> 4) << 4);
    const uint4* btw = g_bf4 + (size_t)ngrp * 128 + lane;   // + c*1024 + k0*256 + pair*32

    float acc[7][4];
#pragma unroll
    for (int n = 0; n < 7; n++)
#pragma unroll
        for (int j = 0; j < 4; j++) acc[n][j] = 0.f;
    float tacc[4] = {0.f, 0.f, 0.f, 0.f};

    // ---------------- prologue: G(0), G(1); input pair 0 ----------------
    float4 va[8];
#pragma unroll
    for (int sub = 0; sub < 2; sub++)
#pragma unroll
        for (int j = 0; j < 4; j++)
            va[sub * 4 + j] = *(const float4*)(ipt + sub * 64 + j * (16 * E_DIM));
#pragma unroll
    for (int s = 0; s < 2; s++) {
        uint32_t gs = gbase + s * GSTAGE;
#pragma unroll
        for (int i = 0; i < 4; i++) {
            cp_async16(gs + gdst[i],       embB + gsrc[i] + s * 512);
            cp_async16(gs + gdst[i] + 256, embB + gsrc[i] + s * 512 + 256);
        }
        CP_COMMIT();
    }

    // ---------------- main loop: 4 iterations of K=128 ----------------
#pragma unroll
    for (int ip = 0; ip < 4; ip++) {
        const int st = ip & 1;
        CP_WAIT1();                     // forces G(ip); G(ip+1) outstanding
        // dot (LDS f32 gather x va regs) + convert + STS both A sub-tiles
        {
            char* adst = ap + st * APAIR + asts;
            const char* gsp = gp + st * GSTAGE + rg * 512 + l4 * 16;
#pragma unroll
            for (int sub = 0; sub < 2; sub++)
#pragma unroll
                for (int j = 0; j < 4; j++) {
                    float4 v = va[sub * 4 + j];
                    float4 gv = *(const float4*)(gsp + sub * 256 + j * (16 * 512));
                    tacc[j] += v.x * gv.x + v.y * gv.y + v.z * gv.z + v.w * gv.w;
                    *(uint2*)(adst + sub * ASUB + j * (16 * ASTR)) = cvt_bf16x4(v);
                }
        }
        if (ip < 3) {                   // input LDG pair ip+1 (1 long iter cover)
            const int ko = (ip + 1) * 128;
#pragma unroll
            for (int sub = 0; sub < 2; sub++)
#pragma unroll
                for (int j = 0; j < 4; j++)
                    va[sub * 4 + j] = *(const float4*)(ipt + ko + sub * 64 + j * (16 * E_DIM));
        }
        __syncthreads();                // A(ip) visible; all G(ip) reads done
        // commit G(ip+2) into stage st (reads of this stage complete CTA-wide)
        if (ip < 2) {
            uint32_t gs = gbase + st * GSTAGE;
#pragma unroll
            for (int i = 0; i < 4; i++) {
                cp_async16(gs + gdst[i],       embB + gsrc[i] + (ip + 2) * 512);
                cp_async16(gs + gdst[i] + 256, embB + gsrc[i] + (ip + 2) * 512 + 256);
            }
        }
        CP_COMMIT();                    // always (uniform group counting)
        // MMA both sub-chunks: A from smem, B from fragment table
#pragma unroll
        for (int sub = 0; sub < 2; sub++) {
            const uint32_t ab = abase + st * APAIR + sub * ASUB + a_woff;
            const uint4* btc = btw + (size_t)(ip * 2 + sub) * 1024;
#pragma unroll
            for (int k0 = 0; k0 < 4; k0++) {
                uint32_t a[4];
                ldmatrix_x4(a[0], a[1], a[2], a[3], ab + k0 * 32);
                uint4 p0 = btc[k0 * 256];
                uint4 p1 = btc[k0 * 256 + 32];
                uint4 p2 = btc[k0 * 256 + 64];
                uint4 p3 = btc[k0 * 256 + 96];
                mma16816(acc[0], a, p0.x, p0.y);
                mma16816(acc[1], a, p0.z, p0.w);
                mma16816(acc[2], a, p1.x, p1.y);
                mma16816(acc[3], a, p1.z, p1.w);
                mma16816(acc[4], a, p2.x, p2.y);
                mma16816(acc[5], a, p2.z, p2.w);
                mma16816(acc[6], a, p3.x, p3.y);
            }
        }
    }

    // --- finish exact target dots (reduce over the 16 k-slot lanes) ---
#pragma unroll
    for (int j = 0; j < 4; j++) {
        float v = tacc[j];
        v += __shfl_xor_sync(0xFFFFFFFFu, v, 8);
        v += __shfl_xor_sync(0xFFFFFFFFu, v, 4);
        v += __shfl_xor_sync(0xFFFFFFFFu, v, 2);
        v += __shfl_xor_sync(0xFFFFFFFFu, v, 1);
        if (l4 == 0) s_tdot[rg + 16 * j] = v;
    }

    // --- softplus epilogue (product trick; noise x <= -1.8 always) ---
    {
        const int g = lane >> 2;
        const int tq = lane & 3;
        float plo = 1.f, phi = 1.f;
#pragma unroll
        for (int nt = 0; nt < 7; nt++) {
            float c0 = cs[(ngrp * 7 + nt) * 8 + 2 * tq];
            float c1 = cs[(ngrp * 7 + nt) * 8 + 2 * tq + 1];
            plo *= (1.f + __expf(acc[nt][0] + c0));
            plo *= (1.f + __expf(acc[nt][1] + c1));
            phi *= (1.f + __expf(acc[nt][2] + c0));
            phi *= (1.f + __expf(acc[nt][3] + c1));
        }
        float slo = __logf(plo);
        float shi = __logf(phi);
        slo += __shfl_xor_sync(0xFFFFFFFFu, slo, 1);
        slo += __shfl_xor_sync(0xFFFFFFFFu, slo, 2);
        shi += __shfl_xor_sync(0xFFFFFFFFu, shi, 1);
        shi += __shfl_xor_sync(0xFFFFFFFFu, shi, 2);
        if (tq == 0) {
            s_red[ngrp][m0 + g] = slo;
            s_red[ngrp][m0 + g + 8] = shi;
        }
    }
    __syncthreads();

    // --- per-row combine (+ target slot), block + grid reduce ---
    if (tid < MROWS) {
        float x0 = s_tdot[tid] + s_xc[tid];
        s_fin[tid] = s_red[0][tid] + s_red[1][tid] + softplus_exact(x0) - x0;
    }
    __syncthreads();
    if (tid < 32) {
        float s = s_fin[tid] + s_fin[tid + 32];
        s += __shfl_xor_sync(0xFFFFFFFFu, s, 16);
        s += __shfl_xor_sync(0xFFFFFFFFu, s, 8);
        s += __shfl_xor_sync(0xFFFFFFFFu, s, 4);
        s += __shfl_xor_sync(0xFFFFFFFFu, s, 2);
        s += __shfl_xor_sync(0xFFFFFFFFu, s, 1);
        if (lane == 0) {
            g_part[blockIdx.x] = s;
            __threadfence();
            int old = atomicAdd(&g_ctr, 1);
            s_flag = (old == NBLK - 1);
        }
        __syncwarp();
        if (s_flag) {
            __threadfence();
            float t = 0.f;
#pragma unroll
            for (int k = 0; k < NBLK / 32; k++)
                t += *((volatile float*)&g_part[lane + 32 * k]);
            t += __shfl_xor_sync(0xFFFFFFFFu, t, 16);
            t += __shfl_xor_sync(0xFFFFFFFFu, t, 8);
            t += __shfl_xor_sync(0xFFFFFFFFu, t, 4);
            t += __shfl_xor_sync(0xFFFFFFFFu, t, 2);
            t += __shfl_xor_sync(0xFFFFFFFFu, t, 1);
            if (lane == 0) {
                out[0] = t * (1.0f / (float)BLROWS);
                g_ctr = 0;
            }
        }
    }
}

// ---------------------------------------------------------------------------
extern "C" void kernel_launch(void* const* d_in, const int* in_sizes, int n_in,
                              void* d_out, int out_size) {
    const float* inp  = (const float*)d_in[0];
    const float* emb  = (const float*)d_in[1];
    const float* bias = (const float*)d_in[2];
    const float* lpn  = (const float*)d_in[3];
    const int*   tgt  = (const int*)  d_in[4];
    const int*   nidx = (const int*)  d_in[5];
    float* out = (float*)d_out;

    const int DSM = 1024 + 2 * APAIR + 2 * GSTAGE;   // 103424 B -> 2 CTAs/SM
    cudaFuncSetAttribute(mega_kernel, cudaFuncAttributeMaxDynamicSharedMemorySize, DSM);

    prep_kernel<<<128, 256>>>(emb, nidx);
    mega_kernel<<<NBLK, 256, DSM>>>(inp, emb, bias, lpn, tgt, nidx, out);
}